// round 5
// baseline (speedup 1.0000x reference)
#include <cuda_runtime.h>

#define FULL 0xffffffffu

// ---------------- scratch ----------------------------------------------------
__device__ float g_F[81 * 8];     // grid evaluations of <Z_j>, layout [n][j]

// ---------------- warp statevector simulation (gridsim only) ----------------
struct St { float2 a[8]; };

__device__ __forceinline__ float2 shxor(float2 v, int m) {
    float2 r;
    r.x = __shfl_xor_sync(FULL, v.x, m);
    r.y = __shfl_xor_sync(FULL, v.y, m);
    return r;
}

template<int Q>
__device__ __forceinline__ void gateRY(St& st, float c, float s, int lane) {
    if constexpr (Q >= 5) {
        constexpr int bit = 1 << (7 - Q);
#pragma unroll
        for (int m = 0; m < 8; ++m) {
            if ((m & bit) == 0) {
                float2 a = st.a[m], b = st.a[m | bit];
                st.a[m]       = make_float2(c * a.x - s * b.x, c * a.y - s * b.y);
                st.a[m | bit] = make_float2(s * a.x + c * b.x, s * a.y + c * b.y);
            }
        }
    } else {
        constexpr int lm = 1 << (4 - Q);
        float sg = (lane & lm) ? s : -s;
#pragma unroll
        for (int m = 0; m < 8; ++m) {
            float2 o = shxor(st.a[m], lm);
            float2 a = st.a[m];
            st.a[m] = make_float2(c * a.x + sg * o.x, c * a.y + sg * o.y);
        }
    }
}

template<int Q>
__device__ __forceinline__ void gateRX(St& st, float c, float s, int lane) {
    if constexpr (Q >= 5) {
        constexpr int bit = 1 << (7 - Q);
#pragma unroll
        for (int m = 0; m < 8; ++m) {
            if ((m & bit) == 0) {
                float2 a = st.a[m], b = st.a[m | bit];
                st.a[m]       = make_float2(c * a.x + s * b.y, c * a.y - s * b.x);
                st.a[m | bit] = make_float2(c * b.x + s * a.y, c * b.y - s * a.x);
            }
        }
    } else {
        constexpr int lm = 1 << (4 - Q);
#pragma unroll
        for (int m = 0; m < 8; ++m) {
            float2 o = shxor(st.a[m], lm);
            float2 a = st.a[m];
            st.a[m] = make_float2(c * a.x + s * o.y, c * a.y - s * o.x);
        }
    }
}

template<int Q>
__device__ __forceinline__ void gateRZ(St& st, float c, float s, int lane) {
    if constexpr (Q >= 5) {
        constexpr int bit = 1 << (7 - Q);
#pragma unroll
        for (int m = 0; m < 8; ++m) {
            float f = (m & bit) ? s : -s;
            float2 a = st.a[m];
            st.a[m] = make_float2(c * a.x - f * a.y, c * a.y + f * a.x);
        }
    } else {
        constexpr int lm = 1 << (4 - Q);
        float f = (lane & lm) ? s : -s;
#pragma unroll
        for (int m = 0; m < 8; ++m) {
            float2 a = st.a[m];
            st.a[m] = make_float2(c * a.x - f * a.y, c * a.y + f * a.x);
        }
    }
}

template<int C, int T>
__device__ __forceinline__ void cnot(St& st, int lane) {
    if constexpr (C <= 4 && T <= 4) {
        constexpr int cm = 1 << (4 - C);
        constexpr int tm = 1 << (4 - T);
        bool ctrl = (lane & cm) != 0;
#pragma unroll
        for (int m = 0; m < 8; ++m) {
            float2 o = shxor(st.a[m], tm);
            if (ctrl) st.a[m] = o;
        }
    } else if constexpr (C <= 4 && T >= 5) {
        constexpr int cm = 1 << (4 - C);
        constexpr int tb = 1 << (7 - T);
        bool ctrl = (lane & cm) != 0;
#pragma unroll
        for (int m = 0; m < 8; ++m) {
            if ((m & tb) == 0) {
                float2 a = st.a[m], b = st.a[m | tb];
                st.a[m]      = ctrl ? b : a;
                st.a[m | tb] = ctrl ? a : b;
            }
        }
    } else {
        constexpr int cb = 1 << (7 - C);
        constexpr int tb = 1 << (7 - T);
#pragma unroll
        for (int m = 0; m < 8; ++m) {
            if ((m & cb) != 0 && (m & tb) == 0) {
                float2 t = st.a[m];
                st.a[m] = st.a[m | tb];
                st.a[m | tb] = t;
            }
        }
    }
}

template<int J>
__device__ __forceinline__ void ansatzStep(St& st, const float* cw, const float* sw, int lane) {
    constexpr int C = (J < 7) ? J : 0;
    constexpr int T = (J < 7) ? J + 1 : 7;
    float c = cw[J], s = sw[J];
    gateRX<J>(st, c, s, lane);
    cnot<C, T>(st, lane);
    gateRY<J>(st, c, s, lane);
    cnot<C, T>(st, lane);
    gateRZ<J>(st, c, s, lane);
}

__device__ __forceinline__ void ansatz(St& st, const float* cw, const float* sw, int lane) {
    ansatzStep<0>(st, cw, sw, lane);
    ansatzStep<1>(st, cw, sw, lane);
    ansatzStep<2>(st, cw, sw, lane);
    ansatzStep<3>(st, cw, sw, lane);
    ansatzStep<4>(st, cw, sw, lane);
    ansatzStep<5>(st, cw, sw, lane);
    ansatzStep<6>(st, cw, sw, lane);
    ansatzStep<7>(st, cw, sw, lane);
}

// ---------------- kernel 1: 81 grid circuits (each block self-contained) ----
__global__ void gridsim_kernel(const float* __restrict__ weights,
                               const float* __restrict__ db,
                               float* __restrict__ out) {
    __shared__ float cw[24], sw[24];
    int lane = threadIdx.x;

    if (blockIdx.x == 0) out[lane] = db[0];   // seed output with bias

    if (lane < 24) {
        const float TWO_PI = 6.28318530717958647692f;
        float w = weights[lane];
        float wm = fmodf(w, TWO_PI);
        if (wm < 0.f) wm += TWO_PI;
        cw[lane] = cosf(0.5f * wm);
        sw[lane] = sinf(0.5f * wm);
    }
    __syncwarp();

    St st;
#pragma unroll
    for (int m = 0; m < 8; ++m) st.a[m] = make_float2(0.f, 0.f);
    if (lane == 0) st.a[0] = make_float2(1.f, 0.f);
    ansatz(st, &cw[0], &sw[0], lane);

    const float GC[3] = {1.f, 0.70710678118654752440f, 0.f};
    const float GS[3] = {0.f, 0.70710678118654752440f, 1.f};
    int n = blockIdx.x;
    int k0 = n / 27, k1 = (n / 9) % 3, k2 = (n / 3) % 3, k3 = n % 3;
    gateRY<0>(st, GC[k0], GS[k0], lane);
    gateRY<1>(st, GC[k1], GS[k1], lane);
    gateRY<2>(st, GC[k2], GS[k2], lane);
    gateRY<3>(st, GC[k3], GS[k3], lane);

    ansatz(st, &cw[8],  &sw[8],  lane);
    ansatz(st, &cw[16], &sw[16], lane);

    float vj[8];
#pragma unroll
    for (int j = 0; j < 8; ++j) vj[j] = 0.f;
#pragma unroll
    for (int m = 0; m < 8; ++m) {
        float2 a = st.a[m];
        float p = a.x * a.x + a.y * a.y;
        int idx = (lane << 3) | m;
#pragma unroll
        for (int j = 0; j < 8; ++j) vj[j] += ((idx >> (7 - j)) & 1) ? -p : p;
    }
#pragma unroll
    for (int j = 0; j < 8; ++j) {
#pragma unroll
        for (int o = 16; o; o >>= 1) vj[j] += __shfl_xor_sync(FULL, vj[j], o);
    }
    if (lane == 0) {
#pragma unroll
        for (int j = 0; j < 8; ++j) g_F[n * 8 + j] = vj[j];
    }
}

// ---------------- kernel 2: transform + layer1 + layer2 + pool + dense ------
// block = 256 threads = 32 positions x 8 channels; grid (32, 32)
#define CH 32
#define NP (CH + 3)    // 35 layer-1 values (halo)
#define NX (CH + 6)    // 38 x-sincos values

__device__ __forceinline__ void build_t9(float c0, float s0, float c1, float s1,
                                         float c2, float s2, float c3, float s3,
                                         float* t01, float* t23) {
    float t0[3] = {1.f, c0, s0};
    float t1[3] = {1.f, c1, s1};
    float t2[3] = {1.f, c2, s2};
    float t3[3] = {1.f, c3, s3};
#pragma unroll
    for (int i = 0; i < 3; ++i)
#pragma unroll
        for (int j = 0; j < 3; ++j) {
            t01[i * 3 + j] = t0[i] * t1[j];
            t23[i * 3 + j] = t2[i] * t3[j];
        }
}

// one cooperative layer-1 evaluation at halo index k (all lanes of the warp
// MUST enter: shuffles are unconditional; only the store is predicated)
__device__ __forceinline__ void l1_eval(int k, bool valid, int kk, int s0,
                                        const float* coef,
                                        const float* xc, const float* xs,
                                        float* ac, float* as_) {
    int kc_ = valid ? k : 0;                 // clamp smem reads for inactive lanes
    float t01[9], t23[9];
    build_t9(xc[kc_], xs[kc_], xc[kc_ + 1], xs[kc_ + 1],
             xc[kc_ + 2], xs[kc_ + 2], xc[kc_ + 3], xs[kc_ + 3], t01, t23);
    float acc = 0.f;
#pragma unroll
    for (int ii = 0; ii < 9; ++ii) {
        if ((ii & 7) == kk) {                // ii == kk, plus ii==8 on kk==0
            float p = 0.f;
#pragma unroll
            for (int l = 0; l < 9; ++l) p = fmaf(coef[ii * 9 + l], t23[l], p);
            acc = fmaf(t01[ii], p, acc);
        }
    }
    acc += __shfl_xor_sync(FULL, acc, 1);    // warp-uniform: every lane executes
    acc += __shfl_xor_sync(FULL, acc, 2);
    acc += __shfl_xor_sync(FULL, acc, 4);
    if (kk == 0 && valid) {
        int p = s0 - 1 + k;
        float cv = 1.f, sv = 0.f;
        if (p >= 0 && p < 1023) __sincosf(fmaxf(acc, 0.f), &sv, &cv);
        ac[k] = cv; as_[k] = sv;
    }
}

__global__ void __launch_bounds__(256) fused_kernel(const float* __restrict__ x,
                                                    const float* __restrict__ dw,
                                                    float* __restrict__ out) {
    __shared__ float coef[648];          // [ch][81], transformed in place
    __shared__ float xc[NX], xs[NX];     // sincos of input window
    __shared__ float ac[NP], as_[NP];    // sincos of layer-1 relu values
    __shared__ float red[8];

    int t = threadIdx.x;
    int lane = t & 31;
    int warp = t >> 5;
    int b = blockIdx.y;
    int s0 = blockIdx.x * CH;

    // --- load F transposed: coef[j*81+n] = g_F[n*8+j] ---
    for (int i = t; i < 648; i += 256) {
        int j = i / 81, n = i - j * 81;
        coef[i] = g_F[n * 8 + j];
    }
    // --- sincos of x window: x index l = s0-2+k ---
    if (t < NX) {
        int l = s0 - 2 + t;
        float cv = 1.f, sv = 0.f;
        if (l >= 0 && l < 1024) __sincosf(x[b * 1024 + l], &sv, &cv);
        xc[t] = cv; xs[t] = sv;
    }
    __syncthreads();

    // --- transform: per axis {1,cos,sin} extraction, in place (4 passes) ---
#pragma unroll
    for (int a = 0; a < 4; ++a) {
        const int stv = (a == 0) ? 27 : (a == 1) ? 9 : (a == 2) ? 3 : 1;
        if (t < 216) {
            int j = t / 27, r = t - j * 27;
            int base = j * 81 + (r / stv) * (3 * stv) + (r % stv);
            float f0 = coef[base], f1 = coef[base + stv], f2 = coef[base + 2 * stv];
            float kc = 0.5f * (f0 + f2);
            coef[base]           = kc;
            coef[base + stv]     = 0.5f * (f0 - f2);
            coef[base + 2 * stv] = f1 - kc;
        }
        __syncthreads();
    }

    // --- layer 1 (cooperative): octet (8 lanes) per position, 2 uniform passes
    int oct = t >> 3;        // 0..31
    int kk  = t & 7;         // lane within octet = partial-sum index
    l1_eval(oct,      true,           kk, s0, coef, xc, xs, ac, as_);   // k = 0..31
    l1_eval(oct + 32, oct + 32 < NP,  kk, s0, coef, xc, xs, ac, as_);   // k = 32..34
    __syncthreads();

    // --- layer 2: one thread per (position, channel) ---
    int pos = oct;               // 0..31
    int ch  = kk;                // 0..7
    int s   = s0 + pos;
    float t01[9], t23[9];
    build_t9(ac[pos], as_[pos], ac[pos + 1], as_[pos + 1],
             ac[pos + 2], as_[pos + 2], ac[pos + 3], as_[pos + 3], t01, t23);
    const float* sc = &coef[ch * 81];
    float v = 0.f;
#pragma unroll
    for (int i = 0; i < 9; ++i) {
        float p = 0.f;
#pragma unroll
        for (int l = 0; l < 9; ++l) p = fmaf(sc[i * 9 + l], t23[l], p);
        v = fmaf(t01[i], p, v);
    }
    // channel max within octet
    v = fmaxf(v, __shfl_xor_sync(FULL, v, 1));
    v = fmaxf(v, __shfl_xor_sync(FULL, v, 2));
    v = fmaxf(v, __shfl_xor_sync(FULL, v, 4));
    // dense contribution (relu(max) == max(relu))
    float contrib = (ch == 0 && s < 1022) ? fmaxf(v, 0.f) * dw[s] : 0.f;
    contrib += __shfl_xor_sync(FULL, contrib, 8);
    contrib += __shfl_xor_sync(FULL, contrib, 16);
    if (lane == 0) red[warp] = contrib;
    __syncthreads();
    if (warp == 0) {
        float r = (lane < 8) ? red[lane] : 0.f;
        r += __shfl_xor_sync(FULL, r, 1);
        r += __shfl_xor_sync(FULL, r, 2);
        r += __shfl_xor_sync(FULL, r, 4);
        if (lane == 0) atomicAdd(&out[b], r);
    }
}

// ---------------- launch ------------------------------------------------------
extern "C" void kernel_launch(void* const* d_in, const int* in_sizes, int n_in,
                              void* d_out, int out_size) {
    const float* x       = (const float*)d_in[0];   // (32,1024,1)
    const float* weights = (const float*)d_in[1];   // (3,8)
    const float* dw      = (const float*)d_in[2];   // (1022,1)
    const float* db      = (const float*)d_in[3];   // (1,)
    float* out = (float*)d_out;                     // (32,1)

    gridsim_kernel<<<81, 32>>>(weights, db, out);
    dim3 g((1022 + CH - 1) / CH, 32);               // (32, 32)
    fused_kernel<<<g, 256>>>(x, dw, out);
}

// round 6
// speedup vs baseline: 1.2924x; 1.2924x over previous
#include <cuda_runtime.h>

#define FULL 0xffffffffu

// ---------------- scratch ----------------------------------------------------
__device__ float g_F[81 * 8];     // grid evaluations of <Z_j>, layout [n][j]

// ---------------- warp statevector simulation (gridsim only) ----------------
struct St { float2 a[8]; };

__device__ __forceinline__ float2 shxor(float2 v, int m) {
    float2 r;
    r.x = __shfl_xor_sync(FULL, v.x, m);
    r.y = __shfl_xor_sync(FULL, v.y, m);
    return r;
}

template<int Q>
__device__ __forceinline__ void gateRY(St& st, float c, float s, int lane) {
    if constexpr (Q >= 5) {
        constexpr int bit = 1 << (7 - Q);
#pragma unroll
        for (int m = 0; m < 8; ++m) {
            if ((m & bit) == 0) {
                float2 a = st.a[m], b = st.a[m | bit];
                st.a[m]       = make_float2(c * a.x - s * b.x, c * a.y - s * b.y);
                st.a[m | bit] = make_float2(s * a.x + c * b.x, s * a.y + c * b.y);
            }
        }
    } else {
        constexpr int lm = 1 << (4 - Q);
        float sg = (lane & lm) ? s : -s;
#pragma unroll
        for (int m = 0; m < 8; ++m) {
            float2 o = shxor(st.a[m], lm);
            float2 a = st.a[m];
            st.a[m] = make_float2(c * a.x + sg * o.x, c * a.y + sg * o.y);
        }
    }
}

template<int Q>
__device__ __forceinline__ void gateRX(St& st, float c, float s, int lane) {
    if constexpr (Q >= 5) {
        constexpr int bit = 1 << (7 - Q);
#pragma unroll
        for (int m = 0; m < 8; ++m) {
            if ((m & bit) == 0) {
                float2 a = st.a[m], b = st.a[m | bit];
                st.a[m]       = make_float2(c * a.x + s * b.y, c * a.y - s * b.x);
                st.a[m | bit] = make_float2(c * b.x + s * a.y, c * b.y - s * a.x);
            }
        }
    } else {
        constexpr int lm = 1 << (4 - Q);
#pragma unroll
        for (int m = 0; m < 8; ++m) {
            float2 o = shxor(st.a[m], lm);
            float2 a = st.a[m];
            st.a[m] = make_float2(c * a.x + s * o.y, c * a.y - s * o.x);
        }
    }
}

template<int Q>
__device__ __forceinline__ void gateRZ(St& st, float c, float s, int lane) {
    if constexpr (Q >= 5) {
        constexpr int bit = 1 << (7 - Q);
#pragma unroll
        for (int m = 0; m < 8; ++m) {
            float f = (m & bit) ? s : -s;
            float2 a = st.a[m];
            st.a[m] = make_float2(c * a.x - f * a.y, c * a.y + f * a.x);
        }
    } else {
        constexpr int lm = 1 << (4 - Q);
        float f = (lane & lm) ? s : -s;
#pragma unroll
        for (int m = 0; m < 8; ++m) {
            float2 a = st.a[m];
            st.a[m] = make_float2(c * a.x - f * a.y, c * a.y + f * a.x);
        }
    }
}

template<int C, int T>
__device__ __forceinline__ void cnot(St& st, int lane) {
    if constexpr (C <= 4 && T <= 4) {
        constexpr int cm = 1 << (4 - C);
        constexpr int tm = 1 << (4 - T);
        bool ctrl = (lane & cm) != 0;
#pragma unroll
        for (int m = 0; m < 8; ++m) {
            float2 o = shxor(st.a[m], tm);
            if (ctrl) st.a[m] = o;
        }
    } else if constexpr (C <= 4 && T >= 5) {
        constexpr int cm = 1 << (4 - C);
        constexpr int tb = 1 << (7 - T);
        bool ctrl = (lane & cm) != 0;
#pragma unroll
        for (int m = 0; m < 8; ++m) {
            if ((m & tb) == 0) {
                float2 a = st.a[m], b = st.a[m | tb];
                st.a[m]      = ctrl ? b : a;
                st.a[m | tb] = ctrl ? a : b;
            }
        }
    } else {
        constexpr int cb = 1 << (7 - C);
        constexpr int tb = 1 << (7 - T);
#pragma unroll
        for (int m = 0; m < 8; ++m) {
            if ((m & cb) != 0 && (m & tb) == 0) {
                float2 t = st.a[m];
                st.a[m] = st.a[m | tb];
                st.a[m | tb] = t;
            }
        }
    }
}

template<int J>
__device__ __forceinline__ void ansatzStep(St& st, const float* cw, const float* sw, int lane) {
    constexpr int C = (J < 7) ? J : 0;
    constexpr int T = (J < 7) ? J + 1 : 7;
    float c = cw[J], s = sw[J];
    gateRX<J>(st, c, s, lane);
    cnot<C, T>(st, lane);
    gateRY<J>(st, c, s, lane);
    cnot<C, T>(st, lane);
    gateRZ<J>(st, c, s, lane);
}

__device__ __forceinline__ void ansatz(St& st, const float* cw, const float* sw, int lane) {
    ansatzStep<0>(st, cw, sw, lane);
    ansatzStep<1>(st, cw, sw, lane);
    ansatzStep<2>(st, cw, sw, lane);
    ansatzStep<3>(st, cw, sw, lane);
    ansatzStep<4>(st, cw, sw, lane);
    ansatzStep<5>(st, cw, sw, lane);
    ansatzStep<6>(st, cw, sw, lane);
    ansatzStep<7>(st, cw, sw, lane);
}

// ---------------- kernel 1: 81 grid circuits (each block self-contained) ----
__global__ void gridsim_kernel(const float* __restrict__ weights,
                               const float* __restrict__ db,
                               float* __restrict__ out) {
    __shared__ float cw[24], sw[24];
    int lane = threadIdx.x;

    if (blockIdx.x == 0) out[lane] = db[0];   // seed output with bias

    if (lane < 24) {
        const float TWO_PI = 6.28318530717958647692f;
        float w = weights[lane];
        float wm = fmodf(w, TWO_PI);
        if (wm < 0.f) wm += TWO_PI;
        cw[lane] = cosf(0.5f * wm);
        sw[lane] = sinf(0.5f * wm);
    }
    __syncwarp();

    St st;
#pragma unroll
    for (int m = 0; m < 8; ++m) st.a[m] = make_float2(0.f, 0.f);
    if (lane == 0) st.a[0] = make_float2(1.f, 0.f);
    ansatz(st, &cw[0], &sw[0], lane);

    const float GC[3] = {1.f, 0.70710678118654752440f, 0.f};
    const float GS[3] = {0.f, 0.70710678118654752440f, 1.f};
    int n = blockIdx.x;
    int k0 = n / 27, k1 = (n / 9) % 3, k2 = (n / 3) % 3, k3 = n % 3;
    gateRY<0>(st, GC[k0], GS[k0], lane);
    gateRY<1>(st, GC[k1], GS[k1], lane);
    gateRY<2>(st, GC[k2], GS[k2], lane);
    gateRY<3>(st, GC[k3], GS[k3], lane);

    ansatz(st, &cw[8],  &sw[8],  lane);
    ansatz(st, &cw[16], &sw[16], lane);

    float vj[8];
#pragma unroll
    for (int j = 0; j < 8; ++j) vj[j] = 0.f;
#pragma unroll
    for (int m = 0; m < 8; ++m) {
        float2 a = st.a[m];
        float p = a.x * a.x + a.y * a.y;
        int idx = (lane << 3) | m;
#pragma unroll
        for (int j = 0; j < 8; ++j) vj[j] += ((idx >> (7 - j)) & 1) ? -p : p;
    }
#pragma unroll
    for (int j = 0; j < 8; ++j) {
#pragma unroll
        for (int o = 16; o; o >>= 1) vj[j] += __shfl_xor_sync(FULL, vj[j], o);
    }
    if (lane == 0) {
#pragma unroll
        for (int j = 0; j < 8; ++j) g_F[n * 8 + j] = vj[j];
    }
}

// ---------------- kernel 2: transform + layer1 + layer2 + pool + dense ------
// 256 threads; thread = (channel = t&7, pair of positions 2q/2q+1, q = t>>3)
// block covers CH = 64 layer-2 positions; grid (16, 32)
#define CH 64
#define NP (CH + 3)    // 67 layer-1 values (halo)
#define NX (CH + 6)    // 70 x-sincos values

__device__ __forceinline__ void build_t9(const float* cc, const float* ss,
                                         float* t01, float* t23) {
    // window sincos at cc[0..3], ss[0..3]
    float t0[3] = {1.f, cc[0], ss[0]};
    float t1[3] = {1.f, cc[1], ss[1]};
    float t2[3] = {1.f, cc[2], ss[2]};
    float t3[3] = {1.f, cc[3], ss[3]};
#pragma unroll
    for (int i = 0; i < 3; ++i)
#pragma unroll
        for (int j = 0; j < 3; ++j) {
            t01[i * 3 + j] = t0[i] * t1[j];
            t23[i * 3 + j] = t2[i] * t3[j];
        }
}

__global__ void __launch_bounds__(256) fused_kernel(const float* __restrict__ x,
                                                    const float* __restrict__ dw,
                                                    float* __restrict__ out) {
    __shared__ float coef[648];          // [ch][81], transformed in place
    __shared__ float xc[NX], xs[NX];     // sincos of input window
    __shared__ float ac[NP], as_[NP];    // sincos of layer-1 relu values
    __shared__ float red[8];

    int t = threadIdx.x;
    int lane = t & 31;
    int warp = t >> 5;
    int b = blockIdx.y;
    int s0 = blockIdx.x * CH;

    // --- load F transposed: coef[j*81+n] = g_F[n*8+j] ---
    for (int i = t; i < 648; i += 256) {
        int j = i / 81, n = i - j * 81;
        coef[i] = g_F[n * 8 + j];
    }
    // --- sincos of x window: x index l = s0-2+k ---
    if (t < NX) {
        int l = s0 - 2 + t;
        float cv = 1.f, sv = 0.f;
        if (l >= 0 && l < 1024) __sincosf(x[b * 1024 + l], &sv, &cv);
        xc[t] = cv; xs[t] = sv;
    }
    __syncthreads();

    // --- transform: per axis {1,cos,sin} extraction, in place (4 passes) ---
#pragma unroll
    for (int a = 0; a < 4; ++a) {
        const int stv = (a == 0) ? 27 : (a == 1) ? 9 : (a == 2) ? 3 : 1;
        if (t < 216) {
            int j = t / 27, r = t - j * 27;
            int base = j * 81 + (r / stv) * (3 * stv) + (r % stv);
            float f0 = coef[base], f1 = coef[base + stv], f2 = coef[base + 2 * stv];
            float kc = 0.5f * (f0 + f2);
            coef[base]           = kc;
            coef[base + stv]     = 0.5f * (f0 - f2);
            coef[base + 2 * stv] = f1 - kc;
        }
        __syncthreads();
    }

    // --- layer 1: thread-per-position (no shuffles -> no divergence hazards)
    // position p = s0 - 1 + k, window x[p-1..p+2] = xc[k..k+3]
    if (t < NP) {
        int p = s0 - 1 + t;
        float cv = 1.f, sv = 0.f;          // OOB position -> angle 0
        if (p >= 0 && p < 1023) {
            float t01[9], t23[9];
            build_t9(&xc[t], &xs[t], t01, t23);
            float v = 0.f;
#pragma unroll
            for (int i = 0; i < 9; ++i) {
                float pp = 0.f;
#pragma unroll
                for (int l = 0; l < 9; ++l) pp = fmaf(coef[i * 9 + l], t23[l], pp);
                v = fmaf(t01[i], pp, v);
            }
            __sincosf(fmaxf(v, 0.f), &sv, &cv);
        }
        ac[t] = cv; as_[t] = sv;
    }
    __syncthreads();

    // --- layer 2: thread = (2 positions, 1 channel); coef regs-reused ---
    int ch = t & 7;
    int q  = t >> 3;                     // 0..31 -> local positions 2q, 2q+1
    int pA = 2 * q, pB = 2 * q + 1;      // L2 pos s uses ac[(s-s0)..(s-s0)+3]
    float t01a[9], t23a[9], t01b[9], t23b[9];
    build_t9(&ac[pA], &as_[pA], t01a, t23a);
    build_t9(&ac[pB], &as_[pB], t01b, t23b);

    const float* sc = &coef[ch * 81];
    float acc0 = 0.f, acc1 = 0.f;
#pragma unroll
    for (int i = 0; i < 9; ++i) {
        float pa = 0.f, pb = 0.f;
#pragma unroll
        for (int l = 0; l < 9; ++l) {
            float c = sc[i * 9 + l];     // one LDS feeds both positions
            pa = fmaf(c, t23a[l], pa);
            pb = fmaf(c, t23b[l], pb);
        }
        acc0 = fmaf(t01a[i], pa, acc0);
        acc1 = fmaf(t01b[i], pb, acc1);
    }

    // channel max across octet (all 32 lanes execute: warp-uniform)
    acc0 = fmaxf(acc0, __shfl_xor_sync(FULL, acc0, 1));
    acc0 = fmaxf(acc0, __shfl_xor_sync(FULL, acc0, 2));
    acc0 = fmaxf(acc0, __shfl_xor_sync(FULL, acc0, 4));
    acc1 = fmaxf(acc1, __shfl_xor_sync(FULL, acc1, 1));
    acc1 = fmaxf(acc1, __shfl_xor_sync(FULL, acc1, 2));
    acc1 = fmaxf(acc1, __shfl_xor_sync(FULL, acc1, 4));

    // dense contributions (relu(max) == max(relu))
    float contrib = 0.f;
    if (ch == 0) {
        int sA = s0 + pA, sB = s0 + pB;
        if (sA < 1022) contrib += fmaxf(acc0, 0.f) * dw[sA];
        if (sB < 1022) contrib += fmaxf(acc1, 0.f) * dw[sB];
    }
    contrib += __shfl_xor_sync(FULL, contrib, 8);
    contrib += __shfl_xor_sync(FULL, contrib, 16);
    if (lane == 0) red[warp] = contrib;
    __syncthreads();
    if (warp == 0) {
        float r = (lane < 8) ? red[lane] : 0.f;
        r += __shfl_xor_sync(FULL, r, 1);
        r += __shfl_xor_sync(FULL, r, 2);
        r += __shfl_xor_sync(FULL, r, 4);
        if (lane == 0) atomicAdd(&out[b], r);
    }
}

// ---------------- launch ------------------------------------------------------
extern "C" void kernel_launch(void* const* d_in, const int* in_sizes, int n_in,
                              void* d_out, int out_size) {
    const float* x       = (const float*)d_in[0];   // (32,1024,1)
    const float* weights = (const float*)d_in[1];   // (3,8)
    const float* dw      = (const float*)d_in[2];   // (1022,1)
    const float* db      = (const float*)d_in[3];   // (1,)
    float* out = (float*)d_out;                     // (32,1)

    gridsim_kernel<<<81, 32>>>(weights, db, out);
    dim3 g((1022 + CH - 1) / CH, 32);               // (16, 32)
    fused_kernel<<<g, 256>>>(x, dw, out);
}